// round 2
// baseline (speedup 1.0000x reference)
#include <cuda_runtime.h>
#include <cstdint>

// Problem constants (fixed by the reference setup_inputs)
#define NB   8        // batch
#define KF   8        // fragments per pixel
#define HH   256
#define WW   256
#define CC   32       // channels
#define PP   100000   // feature table entries
#define HW   (HH * WW)

// Scratch: features transposed to [P, C] so one fragment's 32 channels are a
// contiguous 128B line. 100000*32*4 = 12.8 MB (mostly L2-resident).
__device__ float g_feat_t[(size_t)PP * CC];

// -------------------------------------------------------------------------
// Kernel 1: transpose features [C, P] -> [P, C] via 32x32 smem tiles.
// grid = P/32 = 3125 blocks, block = (32, 8).
// -------------------------------------------------------------------------
__global__ void feat_transpose_kernel(const float* __restrict__ features) {
    __shared__ float tile[32][33];  // +1 pad: conflict-free transpose
    const int p0 = blockIdx.x * 32;
    const int tx = threadIdx.x;     // 0..31
    const int ty = threadIdx.y;     // 0..7

    // Coalesced reads: for each channel row c, 32 consecutive p.
#pragma unroll
    for (int i = 0; i < 32; i += 8) {
        const int c = ty + i;
        tile[c][tx] = features[(size_t)c * PP + (p0 + tx)];
    }
    __syncthreads();

    // Coalesced writes: each output row p is 32 contiguous channel floats.
#pragma unroll
    for (int i = 0; i < 32; i += 8) {
        const int p = ty + i;
        g_feat_t[(size_t)(p0 + p) * CC + tx] = tile[tx][p];
    }
}

// -------------------------------------------------------------------------
// Kernel 2: alpha compositing.
// One warp per pixel (n,h,w); lane = channel. 8 warps (=8 adjacent w pixels)
// per 256-thread block. Feature gather per fragment is one coalesced 128B
// line from the L2-resident transposed table. Output staged through padded
// smem so stores are 32B-contiguous segments instead of 32 scattered lanes.
// grid = N*H*W/8 = 65536 blocks.
// -------------------------------------------------------------------------
__global__ void __launch_bounds__(256)
composite_kernel(const int* __restrict__ frags,
                 const float* __restrict__ alphas,
                 float* __restrict__ out) {
    const int wid  = threadIdx.x >> 5;   // 0..7 : pixel within block
    const int lane = threadIdx.x & 31;   // channel

    const int pix = blockIdx.x * 8 + wid;        // linear pixel id
    const int w = pix & (WW - 1);
    const int h = (pix >> 8) & (HH - 1);
    const int n = pix >> 16;

    // fragments/alphas layout (N, K, H, W): idx = ((n*K + k)*H + h)*W + w
    const size_t base = (size_t)n * KF * HW + (size_t)h * WW + w;

    float T = 1.0f;    // running transmittance (exclusive)
    float acc = 0.0f;  // this lane's channel accumulator

#pragma unroll
    for (int k = 0; k < KF; ++k) {
        const size_t off = base + (size_t)k * HW;
        const int fr = frags[off];          // warp-broadcast load (int32!)
        float a = alphas[off];              // warp-broadcast load
        const bool valid = (fr >= 0);
        a = valid ? a : 0.0f;
        const int idx = valid ? fr : 0;
        const float wgt = a * T;
        T *= (1.0f - a);
        // Coalesced 128B line: 32 lanes read 32 consecutive channel floats.
        acc += wgt * g_feat_t[(size_t)idx * CC + lane];
    }

    // Stage through smem: s[channel][pixel-in-block], padded to kill conflicts.
    __shared__ float s[CC][9];
    s[lane][wid] = acc;
    __syncthreads();

    // Re-map threads: tid -> (c = tid/8, pj = tid%8). Consecutive tids within
    // a channel write 8 consecutive w -> 32B contiguous store segments.
    const int c  = threadIdx.x >> 3;
    const int pj = threadIdx.x & 7;
    const int pbase = blockIdx.x * 8;
    const int w0 = pbase & (WW - 1);
    const int h0 = (pbase >> 8) & (HH - 1);
    const int n0 = pbase >> 16;
    // output layout (N, C, H, W)
    const size_t o = (((size_t)n0 * CC + c) * HH + h0) * WW + (w0 + pj);
    out[o] = s[c][pj];
}

extern "C" void kernel_launch(void* const* d_in, const int* in_sizes, int n_in,
                              void* d_out, int out_size) {
    const int*   frags    = (const int*)d_in[0];    // int32 (N,K,H,W) — JAX x64 off
    const float* alphas   = (const float*)d_in[1];  // f32   (N,K,H,W)
    const float* features = (const float*)d_in[2];  // f32   (C,P)
    float*       out      = (float*)d_out;          // f32   (N,C,H,W)

    // 1) Transpose feature table into __device__ scratch (graph-capturable).
    feat_transpose_kernel<<<PP / 32, dim3(32, 8)>>>(features);

    // 2) Composite: 8 pixels per block, warp-per-pixel.
    const int num_pixels = NB * HH * WW;           // 524288
    composite_kernel<<<num_pixels / 8, 256>>>(frags, alphas, out);
}

// round 3
// speedup vs baseline: 3.5500x; 3.5500x over previous
#include <cuda_runtime.h>

// Problem constants (fixed by the reference setup_inputs)
#define NB   8        // batch
#define KF   8        // fragments per pixel
#define HH   256
#define WW   256
#define CC   32       // channels
#define PP   100000   // feature table entries
#define HW   (HH * WW)

// Scratch: features transposed to [P, C] so one fragment's 32 channels are a
// contiguous 128B line (and 4 consecutive channels a 16B float4).
__device__ float g_feat_t[(size_t)PP * CC];

// -------------------------------------------------------------------------
// Kernel 1: transpose features [C, P] -> [P, C] via 32x32 smem tiles.
// -------------------------------------------------------------------------
__global__ void feat_transpose_kernel(const float* __restrict__ features) {
    __shared__ float tile[32][33];
    const int p0 = blockIdx.x * 32;
    const int tx = threadIdx.x;     // 0..31
    const int ty = threadIdx.y;     // 0..7
#pragma unroll
    for (int i = 0; i < 32; i += 8) {
        const int c = ty + i;
        tile[c][tx] = features[c * PP + (p0 + tx)];
    }
    __syncthreads();
#pragma unroll
    for (int i = 0; i < 32; i += 8) {
        const int p = ty + i;
        g_feat_t[(p0 + p) * CC + tx] = tile[tx][p];
    }
}

// -------------------------------------------------------------------------
// Kernel 2: alpha compositing. Block = 256 threads = 32 consecutive pixels.
//
// Phase A: warp k loads frag+alpha for 32 pixels of fragment k (coalesced
//          128B loads), precomputes the feature byte-offset, stages in smem.
// Phase B: one warp (thread-per-pixel) runs the sequential transmittance
//          scan, overwriting alpha with the final weight.
// Phase C: warp wid gathers for pixels 4*wid..4*wid+3; lane = psub*8+c4,
//          each lane LDG.128s 4 channels -> 1 instruction = 4 pixel-gathers.
// Phase D: stage accumulators through padded smem; fully coalesced 128B
//          output stores (32 consecutive w per channel row).
// -------------------------------------------------------------------------
__global__ void __launch_bounds__(256)
composite_kernel(const int* __restrict__ frags,
                 const float* __restrict__ alphas,
                 float* __restrict__ out) {
    __shared__ float2 wi[KF][32];     // .x = alpha (then weight), .y = feat offset (int bits)
    __shared__ float  s[CC][33];      // output transpose staging, padded

    const int tid  = threadIdx.x;
    const int wid  = tid >> 5;        // 0..7
    const int lane = tid & 31;

    const int pb = blockIdx.x * 32;   // first pixel of this block (32-aligned in w)
    const int w0 = pb & (WW - 1);
    const int h  = (pb >> 8) & (HH - 1);
    const int n  = pb >> 16;
    const int base = n * (KF * HW) + h * WW + w0;   // all 32-bit arithmetic

    // ---- Phase A: coalesced fragment/alpha loads (warp = fragment k) ----
    {
        const int off = base + wid * HW + lane;
        const int fr  = frags[off];
        float a = alphas[off];
        int fo = fr * CC;
        if (fr < 0) { a = 0.0f; fo = 0; }
        wi[wid][lane] = make_float2(a, __int_as_float(fo));
    }
    __syncthreads();

    // ---- Phase B: transmittance scan, one thread per pixel ----
    if (tid < 32) {
        float T = 1.0f;
#pragma unroll
        for (int k = 0; k < KF; ++k) {
            const float a = wi[k][tid].x;
            wi[k][tid].x = a * T;     // weight = a * exclusive-cumprod(1-a)
            T *= (1.0f - a);
        }
    }
    __syncthreads();

    // ---- Phase C: vectorized gather + accumulate ----
    const int psub = lane >> 3;       // 0..3 : pixel within warp's group
    const int c4   = lane & 7;        // 0..7 : float4 channel group
    const int p    = wid * 4 + psub;  // pixel within block (0..31)

    float4 acc = make_float4(0.f, 0.f, 0.f, 0.f);
#pragma unroll
    for (int k = 0; k < KF; ++k) {
        const float2 v  = wi[k][p];               // broadcast LDS.64
        const float wgt = v.x;
        const int   fo  = __float_as_int(v.y);
        const float4 f = *reinterpret_cast<const float4*>(&g_feat_t[fo + c4 * 4]);
        acc.x = fmaf(wgt, f.x, acc.x);
        acc.y = fmaf(wgt, f.y, acc.y);
        acc.z = fmaf(wgt, f.z, acc.z);
        acc.w = fmaf(wgt, f.w, acc.w);
    }

    // ---- Phase D: smem transpose + coalesced stores ----
    // banks: (132*c4 + 33*j + p) mod 32 = (4*c4 + j + p') distinct per fixed j
    s[c4 * 4 + 0][p] = acc.x;
    s[c4 * 4 + 1][p] = acc.y;
    s[c4 * 4 + 2][p] = acc.z;
    s[c4 * 4 + 3][p] = acc.w;
    __syncthreads();

#pragma unroll
    for (int it = 0; it < 4; ++it) {
        const int c = it * 8 + wid;
        out[((n * CC + c) * HH + h) * WW + w0 + lane] = s[c][lane];
    }
}

extern "C" void kernel_launch(void* const* d_in, const int* in_sizes, int n_in,
                              void* d_out, int out_size) {
    const int*   frags    = (const int*)d_in[0];    // int32 (N,K,H,W)
    const float* alphas   = (const float*)d_in[1];  // f32   (N,K,H,W)
    const float* features = (const float*)d_in[2];  // f32   (C,P)
    float*       out      = (float*)d_out;          // f32   (N,C,H,W)

    feat_transpose_kernel<<<PP / 32, dim3(32, 8)>>>(features);

    const int num_pixels = NB * HH * WW;            // 524288
    composite_kernel<<<num_pixels / 32, 256>>>(frags, alphas, out);
}

// round 4
// speedup vs baseline: 4.1213x; 1.1609x over previous
#include <cuda_runtime.h>
#include <cuda_fp16.h>

// Problem constants (fixed by the reference setup_inputs)
#define NB   8        // batch
#define KF   8        // fragments per pixel
#define HH   256
#define WW   256
#define CC   32       // channels
#define PP   100000   // feature table entries
#define HW   (HH * WW)

#define PXB  64       // pixels per block (composite)
#define SPAD 38       // padded row (floats) for output staging

// Scratch: features transposed to [P, C] in fp16 -> one fragment's 32
// channels are a contiguous 64B row. 100000*32*2 = 6.4 MB (L2-resident).
__device__ __half g_feat_h[(size_t)PP * CC];

// -------------------------------------------------------------------------
// Kernel 1: transpose + convert features [C, P] f32 -> [P, C] fp16.
// -------------------------------------------------------------------------
__global__ void feat_transpose_kernel(const float* __restrict__ features) {
    __shared__ float tile[32][33];
    const int p0 = blockIdx.x * 32;
    const int tx = threadIdx.x;     // 0..31
    const int ty = threadIdx.y;     // 0..7
#pragma unroll
    for (int i = 0; i < 32; i += 8) {
        const int c = ty + i;
        tile[c][tx] = features[c * PP + (p0 + tx)];
    }
    __syncthreads();
#pragma unroll
    for (int i = 0; i < 32; i += 8) {
        const int p = ty + i;       // tx = channel
        g_feat_h[(p0 + p) * CC + tx] = __float2half_rn(tile[tx][p]);
    }
}

// -------------------------------------------------------------------------
// Kernel 2: alpha compositing. Block = 256 threads = 64 consecutive pixels.
//
// A: warp k loads frag+alpha for 64 pixels of fragment k (coalesced),
//    stages (alpha, feat_half_offset) in smem.
// B: threads 0..63 run the sequential transmittance scan (weight = a*T).
// C: warp wid gathers for pixels 8*wid..8*wid+7. lane = p8*4 + c8 loads
//    16B = 8 fp16 channels -> one LDG.128 covers 8 pixel-gathers (one 64B
//    line-touch per pixel-fragment). Convert + FMA in fp32.
// D: stage through padded smem; coalesced 128B STG rows.
// -------------------------------------------------------------------------
__global__ void __launch_bounds__(256)
composite_kernel(const int* __restrict__ frags,
                 const float* __restrict__ alphas,
                 float* __restrict__ out) {
    __shared__ float2 wi[KF][PXB];     // .x = alpha->weight, .y = half-offset bits
    __shared__ float  s[PXB][SPAD];    // staging: s[pixel][channel]

    const int tid  = threadIdx.x;
    const int wid  = tid >> 5;         // 0..7
    const int lane = tid & 31;

    const int pb = blockIdx.x * PXB;   // first pixel (64-aligned in w)
    const int w0 = pb & (WW - 1);
    const int h  = (pb >> 8) & (HH - 1);
    const int n  = pb >> 16;
    const int base = n * (KF * HW) + h * WW + w0;   // 32-bit arithmetic

    // ---- Phase A: coalesced fragment/alpha loads (warp = fragment k) ----
#pragma unroll
    for (int j = 0; j < 2; ++j) {
        const int off = base + wid * HW + j * 32 + lane;
        const int fr  = frags[off];
        float a = alphas[off];
        int fo = fr * CC;              // offset into g_feat_h (half units)
        if (fr < 0) { a = 0.0f; fo = 0; }
        wi[wid][j * 32 + lane] = make_float2(a, __int_as_float(fo));
    }
    __syncthreads();

    // ---- Phase B: transmittance scan, one thread per pixel ----
    if (tid < PXB) {
        float T = 1.0f;
#pragma unroll
        for (int k = 0; k < KF; ++k) {
            const float a = wi[k][tid].x;
            wi[k][tid].x = a * T;      // weight = a * exclusive-cumprod(1-a)
            T *= (1.0f - a);
        }
    }
    __syncthreads();

    // ---- Phase C: fp16 gather (8 pixels per LDG.128) + fp32 accumulate ----
    const int p8 = lane >> 2;          // 0..7 : pixel within warp's group
    const int c8 = lane & 3;           // 0..3 : 8-channel group
    const int p  = wid * 8 + p8;       // pixel within block (0..63)

    float acc[8];
#pragma unroll
    for (int j = 0; j < 8; ++j) acc[j] = 0.0f;

#pragma unroll
    for (int k = 0; k < KF; ++k) {
        const float2 v  = wi[k][p];    // broadcast LDS.64
        const float wgt = v.x;
        const int   fo  = __float_as_int(v.y);
        const uint4 raw = *reinterpret_cast<const uint4*>(&g_feat_h[fo + c8 * 8]);
        const __half2* hp = reinterpret_cast<const __half2*>(&raw);
#pragma unroll
        for (int j = 0; j < 4; ++j) {
            const float2 f = __half22float2(hp[j]);
            acc[2 * j]     = fmaf(wgt, f.x, acc[2 * j]);
            acc[2 * j + 1] = fmaf(wgt, f.y, acc[2 * j + 1]);
        }
    }

    // ---- Phase D: smem transpose + coalesced stores ----
    // Thread owns pixel p, channels c8*8 .. c8*8+7. STS.64 x4 (pad 38 keeps
    // row starts 8B-aligned and conflicts ~2-way max).
#pragma unroll
    for (int j = 0; j < 4; ++j) {
        *reinterpret_cast<float2*>(&s[p][c8 * 8 + 2 * j]) =
            make_float2(acc[2 * j], acc[2 * j + 1]);
    }
    __syncthreads();

    // Warp wid covers channels 4*wid..4*wid+3; lanes span w -> coalesced STG.
#pragma unroll
    for (int cc = 0; cc < 4; ++cc) {
        const int c = wid * 4 + cc;
        const int obase = ((n * CC + c) * HH + h) * WW + w0;
#pragma unroll
        for (int j = 0; j < 2; ++j) {
            out[obase + j * 32 + lane] = s[j * 32 + lane][c];
        }
    }
}

extern "C" void kernel_launch(void* const* d_in, const int* in_sizes, int n_in,
                              void* d_out, int out_size) {
    const int*   frags    = (const int*)d_in[0];    // int32 (N,K,H,W)
    const float* alphas   = (const float*)d_in[1];  // f32   (N,K,H,W)
    const float* features = (const float*)d_in[2];  // f32   (C,P)
    float*       out      = (float*)d_out;          // f32   (N,C,H,W)

    feat_transpose_kernel<<<PP / 32, dim3(32, 8)>>>(features);

    const int num_pixels = NB * HH * WW;            // 524288
    composite_kernel<<<num_pixels / PXB, 256>>>(frags, alphas, out);
}